// round 16
// baseline (speedup 1.0000x reference)
#include <cuda_runtime.h>

// N = 2,000,000 rows. Elementwise Gaussian-splat covariance projection.
// Inputs: rot (N,4) f32, mod (1,) f32, scale (N,2) f32, p_k (N,3) f32,
//         view_matrix (N,16) f32.  Output: A (N,9) f32.
//
// R9 = R8 champion with RPT 2 -> 4 (36 front-batched LDGs/thread) to push
// memory-level parallelism; everything else identical:
//   - all inputs per-thread direct LDGs, front-batched
//   - output staged via smem -> coalesced float4 stores
//   - no cp.async / no reg caps / no cache hints (all proven neutral-negative)

#define TPB 128
#define RPT 4
#define RPB (TPB * RPT)             // 512 rows per block

__global__ __launch_bounds__(TPB)
void splat_cov_kernel(const float4* __restrict__ rot,       // (N,4) as float4
                      const float*  __restrict__ mod,       // (1,)
                      const float2* __restrict__ scale,     // (N,2) as float2
                      const float*  __restrict__ p_k,       // (N,3)
                      const float4* __restrict__ vm4,       // (N,16) as 4x float4
                      float*        __restrict__ out,       // (N,9)
                      int n)
{
    __shared__ float s_o[RPB * 9];   // 18 KB staged output

    const int tid = threadIdx.x;
    const int block_base = blockIdx.x * RPB;
    const int rows = min(RPB, n - block_base);

    const float m = __ldg(mod);

    int idx[RPT];
    bool act[RPT];
    #pragma unroll
    for (int k = 0; k < RPT; k++) {
        idx[k] = block_base + tid + k * TPB;
        act[k] = idx[k] < n;
    }

    // ---- Front-batch ALL global loads (36 LDGs in flight per thread) ----
    float4 q[RPT];
    float2 sc[RPT];
    float4 c0[RPT], c1[RPT], c2[RPT], c3[RPT];
    float  p0[RPT], p1[RPT], p2[RPT];
    #pragma unroll
    for (int k = 0; k < RPT; k++) {
        if (act[k]) {
            q[k]  = rot[idx[k]];
            sc[k] = scale[idx[k]];
            const float4* v = vm4 + (size_t)idx[k] * 4;
            c0[k] = v[0]; c1[k] = v[1]; c2[k] = v[2]; c3[k] = v[3];
            const float* p = p_k + (size_t)idx[k] * 3;
            p0[k] = p[0]; p1[k] = p[1]; p2[k] = p[2];
        }
    }

    #pragma unroll
    for (int k = 0; k < RPT; k++) {
        if (!act[k]) continue;

        float r = q[k].x, x = q[k].y, y = q[k].z, z = q[k].w;

        float R00 = 1.0f - 2.0f * (y * y + z * z);
        float R10 = 2.0f * (x * y + r * z);
        float R20 = 2.0f * (x * z - r * y);
        float R01 = 2.0f * (x * y - r * z);
        float R11 = 1.0f - 2.0f * (x * x + z * z);
        float R21 = 2.0f * (y * z + r * x);

        float s0 = m * sc[k].x;
        float s1 = m * sc[k].y;

        float u0 = s0 * R00, u1 = s0 * R10, u2 = s0 * R20;
        float v0 = s1 * R01, v1 = s1 * R11, v2 = s1 * R21;

        const int lrow = tid + k * TPB;                    // local row in block
        float* o = s_o + lrow * 9;                         // odd stride: conflict-free
        o[0] = c0[k].x * u0 + c1[k].x * u1 + c2[k].x * u2;
        o[1] = c0[k].x * v0 + c1[k].x * v1 + c2[k].x * v2;
        o[2] = c0[k].x * p0[k] + c1[k].x * p1[k] + c2[k].x * p2[k] + c3[k].x;
        o[3] = c0[k].y * u0 + c1[k].y * u1 + c2[k].y * u2;
        o[4] = c0[k].y * v0 + c1[k].y * v1 + c2[k].y * v2;
        o[5] = c0[k].y * p0[k] + c1[k].y * p1[k] + c2[k].y * p2[k] + c3[k].y;
        o[6] = c0[k].z * u0 + c1[k].z * u1 + c2[k].z * u2;
        o[7] = c0[k].z * v0 + c1[k].z * v1 + c2[k].z * v2;
        o[8] = c0[k].z * p0[k] + c1[k].z * p1[k] + c2[k].z * p2[k] + c3[k].z;
    }

    __syncthreads();   // outputs staged

    // ---- Store cooperatively: coalesced float4 stores ----
    {
        const int nfloat = rows * 9;                       // up to 4608
        const size_t out_base = (size_t)block_base * 9;    // 4608*blockIdx -> aligned
        float4* dst = (float4*)(out + out_base);
        const float4* src = (const float4*)s_o;
        const int nvec = nfloat >> 2;                      // up to 1152
        #pragma unroll 4
        for (int t = tid; t < nvec; t += TPB) dst[t] = src[t];
        for (int t = (nvec << 2) + tid; t < nfloat; t += TPB)
            out[out_base + t] = s_o[t];
    }
}

extern "C" void kernel_launch(void* const* d_in, const int* in_sizes, int n_in,
                              void* d_out, int out_size)
{
    const float4* rot   = (const float4*)d_in[0];
    const float*  mod   = (const float*)d_in[1];
    const float2* scale = (const float2*)d_in[2];
    const float*  p_k   = (const float*)d_in[3];
    const float4* vm4   = (const float4*)d_in[4];
    float* out = (float*)d_out;

    int n = in_sizes[0] / 4;   // rot has N*4 elements

    int blocks = (n + RPB - 1) / RPB;
    splat_cov_kernel<<<blocks, TPB>>>(rot, mod, scale, p_k, vm4, out, n);
}

// round 17
// speedup vs baseline: 1.0368x; 1.0368x over previous
#include <cuda_runtime.h>

// N = 2,000,000 rows. Elementwise Gaussian-splat covariance projection.
// Inputs: rot (N,4) f32, mod (1,) f32, scale (N,2) f32, p_k (N,3) f32,
//         view_matrix (N,16) f32.  Output: A (N,9) f32.
//
// R10 = R8 champion (TPB=128, RPT=2, all-direct front-batched LDGs, staged
// float4 stores) with the block barrier replaced by WARP-LOCAL staging:
// warp w computes exactly s_o rows [32w,32w+32) and [128+32w,+32), so it can
// stage and store its own 2x1152B chunks after only __syncwarp(). Warps run
// as independent load->compute->store pipelines; no convoy, reads and writes
// interleave at the DRAM at fine grain.

#define TPB 128
#define RPT 2
#define RPB (TPB * RPT)             // 256 rows per block

__global__ __launch_bounds__(TPB)
void splat_cov_kernel(const float4* __restrict__ rot,       // (N,4) as float4
                      const float*  __restrict__ mod,       // (1,)
                      const float2* __restrict__ scale,     // (N,2) as float2
                      const float*  __restrict__ p_k,       // (N,3)
                      const float4* __restrict__ vm4,       // (N,16) as 4x float4
                      float*        __restrict__ out,       // (N,9)
                      int n)
{
    __shared__ float s_o[RPB * 9];   // 9 KB staged output (warp-private regions)

    const int tid  = threadIdx.x;
    const int warp = tid >> 5;
    const int lane = tid & 31;
    const int block_base = blockIdx.x * RPB;
    const int rows = min(RPB, n - block_base);

    const float m = __ldg(mod);

    int idx[RPT];
    bool act[RPT];
    #pragma unroll
    for (int k = 0; k < RPT; k++) {
        idx[k] = block_base + tid + k * TPB;
        act[k] = idx[k] < n;
    }

    // ---- Front-batch ALL global loads (18 LDGs in flight per thread) ----
    float4 q[RPT];
    float2 sc[RPT];
    float4 c0[RPT], c1[RPT], c2[RPT], c3[RPT];
    float  p0[RPT], p1[RPT], p2[RPT];
    #pragma unroll
    for (int k = 0; k < RPT; k++) {
        if (act[k]) {
            q[k]  = rot[idx[k]];
            sc[k] = scale[idx[k]];
            const float4* v = vm4 + (size_t)idx[k] * 4;
            c0[k] = v[0]; c1[k] = v[1]; c2[k] = v[2]; c3[k] = v[3];
            const float* p = p_k + (size_t)idx[k] * 3;
            p0[k] = p[0]; p1[k] = p[1]; p2[k] = p[2];
        }
    }

    // ---- Compute into warp-private smem region ----
    #pragma unroll
    for (int k = 0; k < RPT; k++) {
        if (!act[k]) continue;

        float r = q[k].x, x = q[k].y, y = q[k].z, z = q[k].w;

        float R00 = 1.0f - 2.0f * (y * y + z * z);
        float R10 = 2.0f * (x * y + r * z);
        float R20 = 2.0f * (x * z - r * y);
        float R01 = 2.0f * (x * y - r * z);
        float R11 = 1.0f - 2.0f * (x * x + z * z);
        float R21 = 2.0f * (y * z + r * x);

        float s0 = m * sc[k].x;
        float s1 = m * sc[k].y;

        float u0 = s0 * R00, u1 = s0 * R10, u2 = s0 * R20;
        float v0 = s1 * R01, v1 = s1 * R11, v2 = s1 * R21;

        const int lrow = tid + k * TPB;                    // local row in block
        float* o = s_o + lrow * 9;                         // odd stride: conflict-free
        o[0] = c0[k].x * u0 + c1[k].x * u1 + c2[k].x * u2;
        o[1] = c0[k].x * v0 + c1[k].x * v1 + c2[k].x * v2;
        o[2] = c0[k].x * p0[k] + c1[k].x * p1[k] + c2[k].x * p2[k] + c3[k].x;
        o[3] = c0[k].y * u0 + c1[k].y * u1 + c2[k].y * u2;
        o[4] = c0[k].y * v0 + c1[k].y * v1 + c2[k].y * v2;
        o[5] = c0[k].y * p0[k] + c1[k].y * p1[k] + c2[k].y * p2[k] + c3[k].y;
        o[6] = c0[k].z * u0 + c1[k].z * u1 + c2[k].z * u2;
        o[7] = c0[k].z * v0 + c1[k].z * v1 + c2[k].z * v2;
        o[8] = c0[k].z * p0[k] + c1[k].z * p1[k] + c2[k].z * p2[k] + c3[k].z;
    }

    __syncwarp();   // warp's own staged rows visible to warp

    // ---- Per-warp coalesced float4 stores of its own 32-row chunks ----
    #pragma unroll
    for (int k = 0; k < RPT; k++) {
        const int rstart = k * TPB + warp * 32;            // first row of chunk
        if (rstart >= rows) continue;
        const int cnt = min(32, rows - rstart);            // rows in this chunk
        const int fbase = rstart * 9;                      // 288*? -> 16B aligned
        const size_t gbase = (size_t)block_base * 9 + fbase;

        if (cnt == 32) {
            // 288 floats = 72 float4, contiguous; lanes stride the chunk
            float4* dst = (float4*)(out + gbase);
            const float4* src = (const float4*)(s_o + fbase);
            #pragma unroll
            for (int t = lane; t < 72; t += 32) dst[t] = src[t];
        } else {
            for (int t = lane; t < cnt * 9; t += 32)
                out[gbase + t] = s_o[fbase + t];
        }
    }
}

extern "C" void kernel_launch(void* const* d_in, const int* in_sizes, int n_in,
                              void* d_out, int out_size)
{
    const float4* rot   = (const float4*)d_in[0];
    const float*  mod   = (const float*)d_in[1];
    const float2* scale = (const float2*)d_in[2];
    const float*  p_k   = (const float*)d_in[3];
    const float4* vm4   = (const float4*)d_in[4];
    float* out = (float*)d_out;

    int n = in_sizes[0] / 4;   // rot has N*4 elements

    int blocks = (n + RPB - 1) / RPB;
    splat_cov_kernel<<<blocks, TPB>>>(rot, mod, scale, p_k, vm4, out, n);
}